// round 15
// baseline (speedup 1.0000x reference)
#include <cuda_runtime.h>

#define D_MODEL 1024
#define N_HEADS 16
#define HEAD    64
#define BATCH   2
#define SEQ     2048
#define M_TOT   (BATCH * SEQ)
#define LOG2E   1.4426950408889634f

// Scratch (harness rules: __device__ globals only)
__device__ float g_qp[M_TOT * D_MODEL];
__device__ float g_kp[M_TOT * D_MODEL];
__device__ float g_vp[M_TOT * D_MODEL];
__device__ int   g_mask_nz;        // monotone OR-flag; replay-idempotent (inputs fixed)

// ---------------------------------------------------------------------------
__device__ __forceinline__ unsigned f2tf(float x) {
    unsigned r;
    asm("cvt.rna.tf32.f32 %0, %1;" : "=r"(r) : "f"(x));
    return r;
}
__device__ __forceinline__ unsigned u2tf(unsigned raw) {   // raw fp32 bits -> tf32 bits
    return f2tf(__uint_as_float(raw));
}

__device__ __forceinline__ void mma8(float* d, const unsigned* a, const unsigned* b) {
    asm volatile(
        "mma.sync.aligned.m16n8k8.row.col.f32.tf32.tf32.f32 "
        "{%0,%1,%2,%3}, {%4,%5,%6,%7}, {%8,%9}, {%0,%1,%2,%3};\n"
        : "+f"(d[0]), "+f"(d[1]), "+f"(d[2]), "+f"(d[3])
        : "r"(a[0]), "r"(a[1]), "r"(a[2]), "r"(a[3]), "r"(b[0]), "r"(b[1]));
}

__device__ __forceinline__ void cp16(unsigned* smem_dst, const void* gsrc) {
    unsigned d = (unsigned)__cvta_generic_to_shared(smem_dst);
    asm volatile("cp.async.cg.shared.global [%0], [%1], 16;\n" :: "r"(d), "l"(gsrc));
}
#define CP_COMMIT asm volatile("cp.async.commit_group;\n" ::: "memory")
#define CP_WAIT0  asm volatile("cp.async.wait_group 0;\n" ::: "memory")

// 2^x, FMA/ALU only (x <= 0, clamped at -115). Degree-4 poly.
__device__ __forceinline__ float fast_exp2(float x) {
    x = fmaxf(x, -115.0f);
    float fy = x + 12582912.0f;
    int   k  = __float_as_int(fy);
    float f  = x - (fy - 12582912.0f);
    float p  = 9.61812e-3f;
    p = fmaf(p, f, 5.55041e-2f);
    p = fmaf(p, f, 2.40226507e-1f);
    p = fmaf(p, f, 6.93147182e-1f);
    p = fmaf(p, f, 1.0f);
    return __int_as_float(__float_as_int(p) + (k << 23));
}

// ---------------------------------------------------------------------------
// Projection GEMM on RAW fp32 inputs (tf32 cvt after LDS). R13-proven config,
// minus the redundant trailing __syncthreads (read-before-overwrite of a
// buffer is already ordered by the NEXT iteration's top-of-loop barrier:
// buffer b written at it+2 fill; all threads passed top barriers of it+1,it+2).
// blockIdx.z==3 slice performs the mask-nonzero scan (folds check_mask launch).
// ---------------------------------------------------------------------------
__global__ __launch_bounds__(256, 2) void proj_tc6(
    const float* __restrict__ x0, const float* __restrict__ x1, const float* __restrict__ x2,
    const float* __restrict__ w0, const float* __restrict__ w1, const float* __restrict__ w2,
    const float* __restrict__ bq, const float* __restrict__ bk, const float* __restrict__ bv,
    float* __restrict__ y0, float* __restrict__ y1, float* __restrict__ y2,
    const int4* __restrict__ maskv)
{
    const int tid = threadIdx.x;
    if (blockIdx.z == 3) {
        // ---- mask scan slice: 256 CTAs x 256 threads, 16 int4 each ----
        const int gid = (blockIdx.y * 8 + blockIdx.x) * 256 + tid;
        int acc = 0;
#pragma unroll
        for (int j = 0; j < 16; j++) {
            int4 v = maskv[(size_t)j * 65536 + gid];
            acc |= v.x | v.y | v.z | v.w;
        }
        acc |= __shfl_xor_sync(0xffffffffu, acc, 16);
        acc |= __shfl_xor_sync(0xffffffffu, acc, 8);
        acc |= __shfl_xor_sync(0xffffffffu, acc, 4);
        acc |= __shfl_xor_sync(0xffffffffu, acc, 2);
        acc |= __shfl_xor_sync(0xffffffffu, acc, 1);
        __shared__ int wsh[8];
        if ((tid & 31) == 0) wsh[tid >> 5] = acc;
        __syncthreads();
        if (tid == 0) {
            int r = 0;
#pragma unroll
            for (int j = 0; j < 8; j++) r |= wsh[j];
            if (r) atomicOr(&g_mask_nz, 1);
        }
        return;
    }

    const int z = blockIdx.z;
    const float* X    = (z == 0) ? x0 : (z == 1) ? x1 : x2;
    const float* W    = (z == 0) ? w0 : (z == 1) ? w1 : w2;
    const float* bias = (z == 0) ? bq : (z == 1) ? bk : bv;
    float*       Y    = (z == 0) ? y0 : (z == 1) ? y1 : y2;
    const float oscale = (z == 0) ? 0.125f * LOG2E : 1.0f;

    extern __shared__ unsigned psm[];
    unsigned* As = psm;             // [2][128*36] raw fp32 bits
    unsigned* Bs = psm + 2 * 4608;

    const int lane = tid & 31, wid = tid >> 5;
    const int wm = wid >> 2, wn = wid & 3;
    const int g = lane >> 2, t = lane & 3;
    const int bm = blockIdx.y * 128, bn = blockIdx.x * 128;

    const int frow = tid >> 3;        // 0..31, +p*32
    const int fc4  = (tid & 7) * 4;   // 0..28

    float acc[4][4][4];
#pragma unroll
    for (int mi = 0; mi < 4; mi++)
#pragma unroll
        for (int nj = 0; nj < 4; nj++)
#pragma unroll
            for (int r = 0; r < 4; r++) acc[mi][nj][r] = 0.0f;

    {
        const float* Xs = X + (size_t)bm * D_MODEL + fc4;
        const float* Ws = W + (size_t)bn * D_MODEL + fc4;
#pragma unroll
        for (int p = 0; p < 4; p++) {
            int row = frow + p * 32;
            cp16(As + row * 36 + fc4, Xs + (size_t)row * D_MODEL);
            cp16(Bs + row * 36 + fc4, Ws + (size_t)row * D_MODEL);
        }
        CP_COMMIT;
    }

    for (int it = 0; it < 32; it++) {
        CP_WAIT0;
        __syncthreads();
        if (it < 31) {
            int buf = (it + 1) & 1;
            int k0 = (it + 1) * 32;
            const float* Xs = X + (size_t)bm * D_MODEL + k0 + fc4;
            const float* Ws = W + (size_t)bn * D_MODEL + k0 + fc4;
            unsigned* Ab = As + buf * 4608;
            unsigned* Bb = Bs + buf * 4608;
#pragma unroll
            for (int p = 0; p < 4; p++) {
                int row = frow + p * 32;
                cp16(Ab + row * 36 + fc4, Xs + (size_t)row * D_MODEL);
                cp16(Bb + row * 36 + fc4, Ws + (size_t)row * D_MODEL);
            }
            CP_COMMIT;
        }
        const unsigned* Ab = As + (it & 1) * 4608;
        const unsigned* Bb = Bs + (it & 1) * 4608;
#pragma unroll
        for (int kk = 0; kk < 4; kk++) {
            unsigned af[4][4], bf[4][2];
#pragma unroll
            for (int mi = 0; mi < 4; mi++) {
                int ba = (wm * 64 + mi * 16 + g) * 36 + kk * 8 + t;
                af[mi][0] = u2tf(Ab[ba]);     af[mi][1] = u2tf(Ab[ba + 8 * 36]);
                af[mi][2] = u2tf(Ab[ba + 4]); af[mi][3] = u2tf(Ab[ba + 8 * 36 + 4]);
            }
#pragma unroll
            for (int nj = 0; nj < 4; nj++) {
                int bb = (wn * 32 + nj * 8 + g) * 36 + kk * 8 + t;
                bf[nj][0] = u2tf(Bb[bb]); bf[nj][1] = u2tf(Bb[bb + 4]);
            }
#pragma unroll
            for (int mi = 0; mi < 4; mi++)
#pragma unroll
                for (int nj = 0; nj < 4; nj++)
                    mma8(acc[mi][nj], af[mi], bf[nj]);
        }
        // (no trailing __syncthreads: next write to this buffer is 2 iters away,
        //  already ordered by the intervening top-of-loop barriers)
    }

#pragma unroll
    for (int mi = 0; mi < 4; mi++) {
        int r0 = bm + wm * 64 + mi * 16 + g;
#pragma unroll
        for (int nj = 0; nj < 4; nj++) {
            int c = bn + wn * 32 + nj * 8 + 2 * t;
            float bb0 = bias[c], bb1 = bias[c + 1];
            float v0 = (acc[mi][nj][0] + bb0) * oscale;
            float v1 = (acc[mi][nj][1] + bb1) * oscale;
            float v2 = (acc[mi][nj][2] + bb0) * oscale;
            float v3 = (acc[mi][nj][3] + bb1) * oscale;
            *(float2*)(Y + (size_t)r0 * D_MODEL + c) =
                make_float2(__uint_as_float(f2tf(v0)), __uint_as_float(f2tf(v1)));
            *(float2*)(Y + (size_t)(r0 + 8) * D_MODEL + c) =
                make_float2(__uint_as_float(f2tf(v2)), __uint_as_float(f2tf(v3)));
        }
    }
}

// ---------------------------------------------------------------------------
// Flash attention (byte-identical to R10/R13 = proven 495.6us config).
// exp2-domain online softmax, deferred l-reduction, maskless mask-add skip.
// 256 thr / 8 warps, q-tile 128 (16 rows/warp), key tiles of 64,
// double-buffered cp.async. Strides: Q/K 68, V 72 -> conflict-free.
// ---------------------------------------------------------------------------
__device__ __forceinline__ void p_relayout(const float* s, unsigned* a, int lane, int t) {
    const int srcA = (lane & 28) | (t >> 1);
    const int srcB = srcA + 2;
    float u0 = __shfl_sync(0xffffffffu, s[0], srcA);
    float u1 = __shfl_sync(0xffffffffu, s[1], srcA);
    float v0 = __shfl_sync(0xffffffffu, s[2], srcA);
    float v1 = __shfl_sync(0xffffffffu, s[3], srcA);
    float w0 = __shfl_sync(0xffffffffu, s[0], srcB);
    float w1 = __shfl_sync(0xffffffffu, s[1], srcB);
    float x0 = __shfl_sync(0xffffffffu, s[2], srcB);
    float x1 = __shfl_sync(0xffffffffu, s[3], srcB);
    bool odd = (t & 1);
    a[0] = f2tf(odd ? u1 : u0);
    a[1] = f2tf(odd ? v1 : v0);
    a[2] = f2tf(odd ? w1 : w0);
    a[3] = f2tf(odd ? x1 : x0);
}

__global__ __launch_bounds__(256, 2) void attn_tc4(
    const float* __restrict__ QP, const float* __restrict__ KP,
    const float* __restrict__ VP, const float* __restrict__ mask,
    float* __restrict__ out)
{
    extern __shared__ unsigned smbuf[];
    unsigned* Qs = smbuf;             // 128*68 = 8704 words
    unsigned* Ks = smbuf + 8704;      // 2 x 64*68 (4352 each)
    unsigned* Vs = smbuf + 17408;     // 2 x 64*72 (4608 each)

    const int tid = threadIdx.x, lane = tid & 31, wid = tid >> 5;
    const int g = lane >> 2, t = lane & 3;
    const int rw = wid * 16;
    const int q0 = blockIdx.x * 128;
    const int h = blockIdx.y, b = blockIdx.z;
    const size_t base = (size_t)b * SEQ * D_MODEL + (size_t)h * HEAD;
    const int has_mask = g_mask_nz;

    const int frow = tid >> 4;        // 0..15
    const int fc4  = (tid & 15) * 4;  // 0..60

    {
        const float* Qsrc = QP + base + (size_t)q0 * D_MODEL + fc4;
#pragma unroll
        for (int p = 0; p < 8; p++) {
            int row = frow + p * 16;
            cp16(Qs + row * 68 + fc4, Qsrc + (size_t)row * D_MODEL);
        }
        const float* Ksrc = KP + base + fc4;
        const float* Vsrc = VP + base + fc4;
#pragma unroll
        for (int p = 0; p < 4; p++) {
            int row = frow + p * 16;
            cp16(Ks + row * 68 + fc4, Ksrc + (size_t)row * D_MODEL);
            cp16(Vs + row * 72 + fc4, Vsrc + (size_t)row * D_MODEL);
        }
        CP_COMMIT;
    }

    float o[8][4];
#pragma unroll
    for (int nj = 0; nj < 8; nj++)
#pragma unroll
        for (int r = 0; r < 4; r++) o[nj][r] = 0.0f;
    float m0 = -1e30f, m1 = -1e30f;
    float l0 = 0.0f, l1 = 0.0f;   // lane-partial (reduced across t-lanes at end)

    const float* mp0 = mask + (size_t)(q0 + rw + g) * SEQ;
    const float* mp1 = mp0 + (size_t)8 * SEQ;

    for (int it = 0; it < SEQ / 64; it++) {
        CP_WAIT0;
        __syncthreads();
        if (it + 1 < SEQ / 64) {
            int buf = (it + 1) & 1;
            const float* Ksrc = KP + base + (size_t)(it + 1) * 64 * D_MODEL + fc4;
            const float* Vsrc = VP + base + (size_t)(it + 1) * 64 * D_MODEL + fc4;
            unsigned* Kb = Ks + buf * 4352;
            unsigned* Vb = Vs + buf * 4608;
#pragma unroll
            for (int p = 0; p < 4; p++) {
                int row = frow + p * 16;
                cp16(Kb + row * 68 + fc4, Ksrc + (size_t)row * D_MODEL);
                cp16(Vb + row * 72 + fc4, Vsrc + (size_t)row * D_MODEL);
            }
            CP_COMMIT;
        }
        const unsigned* Kc = Ks + (it & 1) * 4352;
        const unsigned* Vc = Vs + (it & 1) * 4608;
        const int k0 = it * 64;

        // ---- S = Q @ K^T (scores in exp2 domain; Q prescaled) ----
        float s[8][4];
#pragma unroll
        for (int nj = 0; nj < 8; nj++)
#pragma unroll
            for (int r = 0; r < 4; r++) s[nj][r] = 0.0f;

#pragma unroll
        for (int kc = 0; kc < 8; kc++) {
            unsigned a[4];
            int qb = (rw + g) * 68 + kc * 8 + t;
            a[0] = Qs[qb];     a[1] = Qs[qb + 8 * 68];
            a[2] = Qs[qb + 4]; a[3] = Qs[qb + 8 * 68 + 4];
#pragma unroll
            for (int nj = 0; nj < 8; nj++) {
                unsigned bf[2];
                int kb = (nj * 8 + g) * 68 + kc * 8 + t;
                bf[0] = Kc[kb]; bf[1] = Kc[kb + 4];
                mma8(s[nj], a, bf);
            }
        }

        // ---- mask (only if nonzero) + row max ----
        float mx0 = -1e30f, mx1 = -1e30f;
        if (has_mask) {
#pragma unroll
            for (int nj = 0; nj < 8; nj++) {
                float2 mk0 = *(const float2*)(mp0 + k0 + nj * 8 + 2 * t);
                float2 mk1 = *(const float2*)(mp1 + k0 + nj * 8 + 2 * t);
                s[nj][0] = fmaf(mk0.x, LOG2E, s[nj][0]);
                s[nj][1] = fmaf(mk0.y, LOG2E, s[nj][1]);
                s[nj][2] = fmaf(mk1.x, LOG2E, s[nj][2]);
                s[nj][3] = fmaf(mk1.y, LOG2E, s[nj][3]);
                mx0 = fmaxf(mx0, fmaxf(s[nj][0], s[nj][1]));
                mx1 = fmaxf(mx1, fmaxf(s[nj][2], s[nj][3]));
            }
        } else {
#pragma unroll
            for (int nj = 0; nj < 8; nj++) {
                mx0 = fmaxf(mx0, fmaxf(s[nj][0], s[nj][1]));
                mx1 = fmaxf(mx1, fmaxf(s[nj][2], s[nj][3]));
            }
        }
        mx0 = fmaxf(mx0, __shfl_xor_sync(0xffffffffu, mx0, 1));
        mx0 = fmaxf(mx0, __shfl_xor_sync(0xffffffffu, mx0, 2));
        mx1 = fmaxf(mx1, __shfl_xor_sync(0xffffffffu, mx1, 1));
        mx1 = fmaxf(mx1, __shfl_xor_sync(0xffffffffu, mx1, 2));

        float mn0 = fmaxf(m0, mx0), mn1 = fmaxf(m1, mx1);
        float c0 = fast_exp2(m0 - mn0), c1 = fast_exp2(m1 - mn1);
        float sum0 = 0.0f, sum1 = 0.0f;
#pragma unroll
        for (int nj = 0; nj < 8; nj++) {
            s[nj][0] = fast_exp2(s[nj][0] - mn0);
            s[nj][1] = fast_exp2(s[nj][1] - mn0);
            s[nj][2] = fast_exp2(s[nj][2] - mn1);
            s[nj][3] = fast_exp2(s[nj][3] - mn1);
            sum0 += s[nj][0] + s[nj][1];
            sum1 += s[nj][2] + s[nj][3];
        }
        l0 = l0 * c0 + sum0;  l1 = l1 * c1 + sum1;
        m0 = mn0;             m1 = mn1;
#pragma unroll
        for (int nj = 0; nj < 8; nj++) {
            o[nj][0] *= c0; o[nj][1] *= c0;
            o[nj][2] *= c1; o[nj][3] *= c1;
        }

        // ---- O += P @ V (P via shfl relayout) ----
#pragma unroll
        for (int kp = 0; kp < 4; kp++) {
            unsigned pe[4], po[4];
            p_relayout(s[2 * kp],     pe, lane, t);
            p_relayout(s[2 * kp + 1], po, lane, t);
#pragma unroll
            for (int oj = 0; oj < 8; oj++) {
                unsigned bA[2], bB[2];
                int vb = (kp * 16 + t) * 72 + oj * 8 + g;
                bA[0] = Vc[vb];           bA[1] = Vc[vb + 4 * 72];
                bB[0] = Vc[vb + 8 * 72];  bB[1] = Vc[vb + 12 * 72];
                mma8(o[oj], pe, bA);
                mma8(o[oj], po, bB);
            }
        }
    }

    // final cross-lane reduction of deferred l
    l0 += __shfl_xor_sync(0xffffffffu, l0, 1);
    l0 += __shfl_xor_sync(0xffffffffu, l0, 2);
    l1 += __shfl_xor_sync(0xffffffffu, l1, 1);
    l1 += __shfl_xor_sync(0xffffffffu, l1, 2);

    float inv0 = 1.0f / l0, inv1 = 1.0f / l1;
    const int r0g = q0 + rw + g;
    float* o0 = out + base + (size_t)r0g * D_MODEL;
    float* o1 = o0 + (size_t)8 * D_MODEL;
#pragma unroll
    for (int nj = 0; nj < 8; nj++) {
        *(float2*)(o0 + nj * 8 + 2 * t) = make_float2(o[nj][0] * inv0, o[nj][1] * inv0);
        *(float2*)(o1 + nj * 8 + 2 * t) = make_float2(o[nj][2] * inv1, o[nj][3] * inv1);
    }
}

// ---------------------------------------------------------------------------

extern "C" void kernel_launch(void* const* d_in, const int* in_sizes, int n_in,
                              void* d_out, int out_size)
{
    const float* q    = (const float*)d_in[0];
    const float* k    = (const float*)d_in[1];
    const float* v    = (const float*)d_in[2];
    const float* mask = (const float*)d_in[3];
    const float* Wq   = (const float*)d_in[4];
    const float* bq   = (const float*)d_in[5];
    const float* Wk   = (const float*)d_in[6];
    const float* bk   = (const float*)d_in[7];
    const float* Wv   = (const float*)d_in[8];
    const float* bv   = (const float*)d_in[9];
    float* out = (float*)d_out;

    float *qp, *kp, *vp;
    cudaGetSymbolAddress((void**)&qp, g_qp);
    cudaGetSymbolAddress((void**)&kp, g_kp);
    cudaGetSymbolAddress((void**)&vp, g_vp);

    const int psmem = 4 * 4608 * (int)sizeof(unsigned);   // 73728 B
    cudaFuncSetAttribute(proj_tc6, cudaFuncAttributeMaxDynamicSharedMemorySize, psmem);
    proj_tc6<<<dim3(D_MODEL / 128, M_TOT / 128, 4), 256, psmem>>>(
        q, k, v, Wq, Wk, Wv, bq, bk, bv, qp, kp, vp, (const int4*)mask);

    const int asmem = (8704 + 2 * 4352 + 2 * 4608) * (int)sizeof(unsigned);  // 106496 B
    cudaFuncSetAttribute(attn_tc4, cudaFuncAttributeMaxDynamicSharedMemorySize, asmem);
    attn_tc4<<<dim3(SEQ / 128, N_HEADS, BATCH), 256, asmem>>>(qp, kp, vp, mask, out);
}

// round 16
// speedup vs baseline: 1.0001x; 1.0001x over previous
#include <cuda_runtime.h>

#define D_MODEL 1024
#define N_HEADS 16
#define HEAD    64
#define BATCH   2
#define SEQ     2048
#define M_TOT   (BATCH * SEQ)
#define LOG2E   1.4426950408889634f

// Scratch (harness rules: __device__ globals only)
__device__ float g_qp[M_TOT * D_MODEL];
__device__ float g_kp[M_TOT * D_MODEL];
__device__ float g_vp[M_TOT * D_MODEL];
__device__ int   g_mask_nz;        // monotone OR-flag; replay-idempotent (inputs fixed)

// ---------------------------------------------------------------------------
__device__ __forceinline__ unsigned f2tf(float x) {
    unsigned r;
    asm("cvt.rna.tf32.f32 %0, %1;" : "=r"(r) : "f"(x));
    return r;
}
__device__ __forceinline__ unsigned u2tf(unsigned raw) {   // raw fp32 bits -> tf32 bits
    return f2tf(__uint_as_float(raw));
}

__device__ __forceinline__ void mma8(float* d, const unsigned* a, const unsigned* b) {
    asm volatile(
        "mma.sync.aligned.m16n8k8.row.col.f32.tf32.tf32.f32 "
        "{%0,%1,%2,%3}, {%4,%5,%6,%7}, {%8,%9}, {%0,%1,%2,%3};\n"
        : "+f"(d[0]), "+f"(d[1]), "+f"(d[2]), "+f"(d[3])
        : "r"(a[0]), "r"(a[1]), "r"(a[2]), "r"(a[3]), "r"(b[0]), "r"(b[1]));
}

__device__ __forceinline__ void cp16(unsigned* smem_dst, const void* gsrc) {
    unsigned d = (unsigned)__cvta_generic_to_shared(smem_dst);
    asm volatile("cp.async.cg.shared.global [%0], [%1], 16;\n" :: "r"(d), "l"(gsrc));
}
#define CP_COMMIT asm volatile("cp.async.commit_group;\n" ::: "memory")
#define CP_WAIT0  asm volatile("cp.async.wait_group 0;\n" ::: "memory")

// 2^x, FMA/ALU only (x <= 0, clamped at -115). Degree-4 poly.
__device__ __forceinline__ float fast_exp2(float x) {
    x = fmaxf(x, -115.0f);
    float fy = x + 12582912.0f;
    int   k  = __float_as_int(fy);
    float f  = x - (fy - 12582912.0f);
    float p  = 9.61812e-3f;
    p = fmaf(p, f, 5.55041e-2f);
    p = fmaf(p, f, 2.40226507e-1f);
    p = fmaf(p, f, 6.93147182e-1f);
    p = fmaf(p, f, 1.0f);
    return __int_as_float(__float_as_int(p) + (k << 23));
}

// ---------------------------------------------------------------------------
// Projection GEMM on RAW fp32 inputs (tf32 cvt after LDS). R13-proven config.
// blockIdx.z==3 slice performs the mask-nonzero scan (folds check_mask launch).
// ---------------------------------------------------------------------------
__global__ __launch_bounds__(256, 2) void proj_tc6(
    const float* __restrict__ x0, const float* __restrict__ x1, const float* __restrict__ x2,
    const float* __restrict__ w0, const float* __restrict__ w1, const float* __restrict__ w2,
    const float* __restrict__ bq, const float* __restrict__ bk, const float* __restrict__ bv,
    float* __restrict__ y0, float* __restrict__ y1, float* __restrict__ y2,
    const int4* __restrict__ maskv)
{
    const int tid = threadIdx.x;
    if (blockIdx.z == 3) {
        // ---- mask scan slice: 256 CTAs x 256 threads, 16 int4 each ----
        const int gid = (blockIdx.y * 8 + blockIdx.x) * 256 + tid;
        int acc = 0;
#pragma unroll
        for (int j = 0; j < 16; j++) {
            int4 v = maskv[(size_t)j * 65536 + gid];
            acc |= v.x | v.y | v.z | v.w;
        }
        acc |= __shfl_xor_sync(0xffffffffu, acc, 16);
        acc |= __shfl_xor_sync(0xffffffffu, acc, 8);
        acc |= __shfl_xor_sync(0xffffffffu, acc, 4);
        acc |= __shfl_xor_sync(0xffffffffu, acc, 2);
        acc |= __shfl_xor_sync(0xffffffffu, acc, 1);
        __shared__ int wsh[8];
        if ((tid & 31) == 0) wsh[tid >> 5] = acc;
        __syncthreads();
        if (tid == 0) {
            int r = 0;
#pragma unroll
            for (int j = 0; j < 8; j++) r |= wsh[j];
            if (r) atomicOr(&g_mask_nz, 1);
        }
        return;
    }

    const int z = blockIdx.z;
    const float* X    = (z == 0) ? x0 : (z == 1) ? x1 : x2;
    const float* W    = (z == 0) ? w0 : (z == 1) ? w1 : w2;
    const float* bias = (z == 0) ? bq : (z == 1) ? bk : bv;
    float*       Y    = (z == 0) ? y0 : (z == 1) ? y1 : y2;
    const float oscale = (z == 0) ? 0.125f * LOG2E : 1.0f;

    extern __shared__ unsigned psm[];
    unsigned* As = psm;             // [2][128*36] raw fp32 bits
    unsigned* Bs = psm + 2 * 4608;

    const int lane = tid & 31, wid = tid >> 5;
    const int wm = wid >> 2, wn = wid & 3;
    const int g = lane >> 2, t = lane & 3;
    const int bm = blockIdx.y * 128, bn = blockIdx.x * 128;

    const int frow = tid >> 3;        // 0..31, +p*32
    const int fc4  = (tid & 7) * 4;   // 0..28

    float acc[4][4][4];
#pragma unroll
    for (int mi = 0; mi < 4; mi++)
#pragma unroll
        for (int nj = 0; nj < 4; nj++)
#pragma unroll
            for (int r = 0; r < 4; r++) acc[mi][nj][r] = 0.0f;

    {
        const float* Xs = X + (size_t)bm * D_MODEL + fc4;
        const float* Ws = W + (size_t)bn * D_MODEL + fc4;
#pragma unroll
        for (int p = 0; p < 4; p++) {
            int row = frow + p * 32;
            cp16(As + row * 36 + fc4, Xs + (size_t)row * D_MODEL);
            cp16(Bs + row * 36 + fc4, Ws + (size_t)row * D_MODEL);
        }
        CP_COMMIT;
    }

    for (int it = 0; it < 32; it++) {
        CP_WAIT0;
        __syncthreads();
        if (it < 31) {
            int buf = (it + 1) & 1;
            int k0 = (it + 1) * 32;
            const float* Xs = X + (size_t)bm * D_MODEL + k0 + fc4;
            const float* Ws = W + (size_t)bn * D_MODEL + k0 + fc4;
            unsigned* Ab = As + buf * 4608;
            unsigned* Bb = Bs + buf * 4608;
#pragma unroll
            for (int p = 0; p < 4; p++) {
                int row = frow + p * 32;
                cp16(Ab + row * 36 + fc4, Xs + (size_t)row * D_MODEL);
                cp16(Bb + row * 36 + fc4, Ws + (size_t)row * D_MODEL);
            }
            CP_COMMIT;
        }
        const unsigned* Ab = As + (it & 1) * 4608;
        const unsigned* Bb = Bs + (it & 1) * 4608;
#pragma unroll
        for (int kk = 0; kk < 4; kk++) {
            unsigned af[4][4], bf[4][2];
#pragma unroll
            for (int mi = 0; mi < 4; mi++) {
                int ba = (wm * 64 + mi * 16 + g) * 36 + kk * 8 + t;
                af[mi][0] = u2tf(Ab[ba]);     af[mi][1] = u2tf(Ab[ba + 8 * 36]);
                af[mi][2] = u2tf(Ab[ba + 4]); af[mi][3] = u2tf(Ab[ba + 8 * 36 + 4]);
            }
#pragma unroll
            for (int nj = 0; nj < 4; nj++) {
                int bb = (wn * 32 + nj * 8 + g) * 36 + kk * 8 + t;
                bf[nj][0] = u2tf(Bb[bb]); bf[nj][1] = u2tf(Bb[bb + 4]);
            }
#pragma unroll
            for (int mi = 0; mi < 4; mi++)
#pragma unroll
                for (int nj = 0; nj < 4; nj++)
                    mma8(acc[mi][nj], af[mi], bf[nj]);
        }
        __syncthreads();
    }

#pragma unroll
    for (int mi = 0; mi < 4; mi++) {
        int r0 = bm + wm * 64 + mi * 16 + g;
#pragma unroll
        for (int nj = 0; nj < 4; nj++) {
            int c = bn + wn * 32 + nj * 8 + 2 * t;
            float bb0 = bias[c], bb1 = bias[c + 1];
            float v0 = (acc[mi][nj][0] + bb0) * oscale;
            float v1 = (acc[mi][nj][1] + bb1) * oscale;
            float v2 = (acc[mi][nj][2] + bb0) * oscale;
            float v3 = (acc[mi][nj][3] + bb1) * oscale;
            *(float2*)(Y + (size_t)r0 * D_MODEL + c) =
                make_float2(__uint_as_float(f2tf(v0)), __uint_as_float(f2tf(v1)));
            *(float2*)(Y + (size_t)(r0 + 8) * D_MODEL + c) =
                make_float2(__uint_as_float(f2tf(v2)), __uint_as_float(f2tf(v3)));
        }
    }
}

// ---------------------------------------------------------------------------
// Flash attention (byte-identical to R10/R13 = proven 495.6us config).
// exp2-domain online softmax, deferred l-reduction, maskless mask-add skip.
// 256 thr / 8 warps, q-tile 128 (16 rows/warp), key tiles of 64,
// double-buffered cp.async. Strides: Q/K 68, V 72 -> conflict-free.
// ---------------------------------------------------------------------------
__device__ __forceinline__ void p_relayout(const float* s, unsigned* a, int lane, int t) {
    const int srcA = (lane & 28) | (t >> 1);
    const int srcB = srcA + 2;
    float u0 = __shfl_sync(0xffffffffu, s[0], srcA);
    float u1 = __shfl_sync(0xffffffffu, s[1], srcA);
    float v0 = __shfl_sync(0xffffffffu, s[2], srcA);
    float v1 = __shfl_sync(0xffffffffu, s[3], srcA);
    float w0 = __shfl_sync(0xffffffffu, s[0], srcB);
    float w1 = __shfl_sync(0xffffffffu, s[1], srcB);
    float x0 = __shfl_sync(0xffffffffu, s[2], srcB);
    float x1 = __shfl_sync(0xffffffffu, s[3], srcB);
    bool odd = (t & 1);
    a[0] = f2tf(odd ? u1 : u0);
    a[1] = f2tf(odd ? v1 : v0);
    a[2] = f2tf(odd ? w1 : w0);
    a[3] = f2tf(odd ? x1 : x0);
}

__global__ __launch_bounds__(256, 2) void attn_tc4(
    const float* __restrict__ QP, const float* __restrict__ KP,
    const float* __restrict__ VP, const float* __restrict__ mask,
    float* __restrict__ out)
{
    extern __shared__ unsigned smbuf[];
    unsigned* Qs = smbuf;             // 128*68 = 8704 words
    unsigned* Ks = smbuf + 8704;      // 2 x 64*68 (4352 each)
    unsigned* Vs = smbuf + 17408;     // 2 x 64*72 (4608 each)

    const int tid = threadIdx.x, lane = tid & 31, wid = tid >> 5;
    const int g = lane >> 2, t = lane & 3;
    const int rw = wid * 16;
    const int q0 = blockIdx.x * 128;
    const int h = blockIdx.y, b = blockIdx.z;
    const size_t base = (size_t)b * SEQ * D_MODEL + (size_t)h * HEAD;
    const int has_mask = g_mask_nz;

    const int frow = tid >> 4;        // 0..15
    const int fc4  = (tid & 15) * 4;  // 0..60

    {
        const float* Qsrc = QP + base + (size_t)q0 * D_MODEL + fc4;
#pragma unroll
        for (int p = 0; p < 8; p++) {
            int row = frow + p * 16;
            cp16(Qs + row * 68 + fc4, Qsrc + (size_t)row * D_MODEL);
        }
        const float* Ksrc = KP + base + fc4;
        const float* Vsrc = VP + base + fc4;
#pragma unroll
        for (int p = 0; p < 4; p++) {
            int row = frow + p * 16;
            cp16(Ks + row * 68 + fc4, Ksrc + (size_t)row * D_MODEL);
            cp16(Vs + row * 72 + fc4, Vsrc + (size_t)row * D_MODEL);
        }
        CP_COMMIT;
    }

    float o[8][4];
#pragma unroll
    for (int nj = 0; nj < 8; nj++)
#pragma unroll
        for (int r = 0; r < 4; r++) o[nj][r] = 0.0f;
    float m0 = -1e30f, m1 = -1e30f;
    float l0 = 0.0f, l1 = 0.0f;   // lane-partial (reduced across t-lanes at end)

    const float* mp0 = mask + (size_t)(q0 + rw + g) * SEQ;
    const float* mp1 = mp0 + (size_t)8 * SEQ;

    for (int it = 0; it < SEQ / 64; it++) {
        CP_WAIT0;
        __syncthreads();
        if (it + 1 < SEQ / 64) {
            int buf = (it + 1) & 1;
            const float* Ksrc = KP + base + (size_t)(it + 1) * 64 * D_MODEL + fc4;
            const float* Vsrc = VP + base + (size_t)(it + 1) * 64 * D_MODEL + fc4;
            unsigned* Kb = Ks + buf * 4352;
            unsigned* Vb = Vs + buf * 4608;
#pragma unroll
            for (int p = 0; p < 4; p++) {
                int row = frow + p * 16;
                cp16(Kb + row * 68 + fc4, Ksrc + (size_t)row * D_MODEL);
                cp16(Vb + row * 72 + fc4, Vsrc + (size_t)row * D_MODEL);
            }
            CP_COMMIT;
        }
        const unsigned* Kc = Ks + (it & 1) * 4352;
        const unsigned* Vc = Vs + (it & 1) * 4608;
        const int k0 = it * 64;

        // ---- S = Q @ K^T (scores in exp2 domain; Q prescaled) ----
        float s[8][4];
#pragma unroll
        for (int nj = 0; nj < 8; nj++)
#pragma unroll
            for (int r = 0; r < 4; r++) s[nj][r] = 0.0f;

#pragma unroll
        for (int kc = 0; kc < 8; kc++) {
            unsigned a[4];
            int qb = (rw + g) * 68 + kc * 8 + t;
            a[0] = Qs[qb];     a[1] = Qs[qb + 8 * 68];
            a[2] = Qs[qb + 4]; a[3] = Qs[qb + 8 * 68 + 4];
#pragma unroll
            for (int nj = 0; nj < 8; nj++) {
                unsigned bf[2];
                int kb = (nj * 8 + g) * 68 + kc * 8 + t;
                bf[0] = Kc[kb]; bf[1] = Kc[kb + 4];
                mma8(s[nj], a, bf);
            }
        }

        // ---- mask (only if nonzero) + row max ----
        float mx0 = -1e30f, mx1 = -1e30f;
        if (has_mask) {
#pragma unroll
            for (int nj = 0; nj < 8; nj++) {
                float2 mk0 = *(const float2*)(mp0 + k0 + nj * 8 + 2 * t);
                float2 mk1 = *(const float2*)(mp1 + k0 + nj * 8 + 2 * t);
                s[nj][0] = fmaf(mk0.x, LOG2E, s[nj][0]);
                s[nj][1] = fmaf(mk0.y, LOG2E, s[nj][1]);
                s[nj][2] = fmaf(mk1.x, LOG2E, s[nj][2]);
                s[nj][3] = fmaf(mk1.y, LOG2E, s[nj][3]);
                mx0 = fmaxf(mx0, fmaxf(s[nj][0], s[nj][1]));
                mx1 = fmaxf(mx1, fmaxf(s[nj][2], s[nj][3]));
            }
        } else {
#pragma unroll
            for (int nj = 0; nj < 8; nj++) {
                mx0 = fmaxf(mx0, fmaxf(s[nj][0], s[nj][1]));
                mx1 = fmaxf(mx1, fmaxf(s[nj][2], s[nj][3]));
            }
        }
        mx0 = fmaxf(mx0, __shfl_xor_sync(0xffffffffu, mx0, 1));
        mx0 = fmaxf(mx0, __shfl_xor_sync(0xffffffffu, mx0, 2));
        mx1 = fmaxf(mx1, __shfl_xor_sync(0xffffffffu, mx1, 1));
        mx1 = fmaxf(mx1, __shfl_xor_sync(0xffffffffu, mx1, 2));

        float mn0 = fmaxf(m0, mx0), mn1 = fmaxf(m1, mx1);
        float c0 = fast_exp2(m0 - mn0), c1 = fast_exp2(m1 - mn1);
        float sum0 = 0.0f, sum1 = 0.0f;
#pragma unroll
        for (int nj = 0; nj < 8; nj++) {
            s[nj][0] = fast_exp2(s[nj][0] - mn0);
            s[nj][1] = fast_exp2(s[nj][1] - mn0);
            s[nj][2] = fast_exp2(s[nj][2] - mn1);
            s[nj][3] = fast_exp2(s[nj][3] - mn1);
            sum0 += s[nj][0] + s[nj][1];
            sum1 += s[nj][2] + s[nj][3];
        }
        l0 = l0 * c0 + sum0;  l1 = l1 * c1 + sum1;
        m0 = mn0;             m1 = mn1;
#pragma unroll
        for (int nj = 0; nj < 8; nj++) {
            o[nj][0] *= c0; o[nj][1] *= c0;
            o[nj][2] *= c1; o[nj][3] *= c1;
        }

        // ---- O += P @ V (P via shfl relayout) ----
#pragma unroll
        for (int kp = 0; kp < 4; kp++) {
            unsigned pe[4], po[4];
            p_relayout(s[2 * kp],     pe, lane, t);
            p_relayout(s[2 * kp + 1], po, lane, t);
#pragma unroll
            for (int oj = 0; oj < 8; oj++) {
                unsigned bA[2], bB[2];
                int vb = (kp * 16 + t) * 72 + oj * 8 + g;
                bA[0] = Vc[vb];           bA[1] = Vc[vb + 4 * 72];
                bB[0] = Vc[vb + 8 * 72];  bB[1] = Vc[vb + 12 * 72];
                mma8(o[oj], pe, bA);
                mma8(o[oj], po, bB);
            }
        }
    }

    // final cross-lane reduction of deferred l
    l0 += __shfl_xor_sync(0xffffffffu, l0, 1);
    l0 += __shfl_xor_sync(0xffffffffu, l0, 2);
    l1 += __shfl_xor_sync(0xffffffffu, l1, 1);
    l1 += __shfl_xor_sync(0xffffffffu, l1, 2);

    float inv0 = 1.0f / l0, inv1 = 1.0f / l1;
    const int r0g = q0 + rw + g;
    float* o0 = out + base + (size_t)r0g * D_MODEL;
    float* o1 = o0 + (size_t)8 * D_MODEL;
#pragma unroll
    for (int nj = 0; nj < 8; nj++) {
        *(float2*)(o0 + nj * 8 + 2 * t) = make_float2(o[nj][0] * inv0, o[nj][1] * inv0);
        *(float2*)(o1 + nj * 8 + 2 * t) = make_float2(o[nj][2] * inv1, o[nj][3] * inv1);
    }
}

// ---------------------------------------------------------------------------

extern "C" void kernel_launch(void* const* d_in, const int* in_sizes, int n_in,
                              void* d_out, int out_size)
{
    const float* q    = (const float*)d_in[0];
    const float* k    = (const float*)d_in[1];
    const float* v    = (const float*)d_in[2];
    const float* mask = (const float*)d_in[3];
    const float* Wq   = (const float*)d_in[4];
    const float* bq   = (const float*)d_in[5];
    const float* Wk   = (const float*)d_in[6];
    const float* bk   = (const float*)d_in[7];
    const float* Wv   = (const float*)d_in[8];
    const float* bv   = (const float*)d_in[9];
    float* out = (float*)d_out;

    float *qp, *kp, *vp;
    cudaGetSymbolAddress((void**)&qp, g_qp);
    cudaGetSymbolAddress((void**)&kp, g_kp);
    cudaGetSymbolAddress((void**)&vp, g_vp);

    const int psmem = 4 * 4608 * (int)sizeof(unsigned);   // 73728 B
    cudaFuncSetAttribute(proj_tc6, cudaFuncAttributeMaxDynamicSharedMemorySize, psmem);
    proj_tc6<<<dim3(D_MODEL / 128, M_TOT / 128, 4), 256, psmem>>>(
        q, k, v, Wq, Wk, Wv, bq, bk, bv, qp, kp, vp, (const int4*)mask);

    const int asmem = (8704 + 2 * 4352 + 2 * 4608) * (int)sizeof(unsigned);  // 106496 B
    cudaFuncSetAttribute(attn_tc4, cudaFuncAttributeMaxDynamicSharedMemorySize, asmem);
    attn_tc4<<<dim3(SEQ / 128, N_HEADS, BATCH), 256, asmem>>>(qp, kp, vp, mask, out);
}

// round 17
// speedup vs baseline: 1.5459x; 1.5458x over previous
#include <cuda_runtime.h>

#define D_MODEL 1024
#define N_HEADS 16
#define HEAD    64
#define BATCH   2
#define SEQ     2048
#define M_TOT   (BATCH * SEQ)
#define LOG2E   1.4426950408889634f

// Scratch (harness rules: __device__ globals only)
__device__ float g_qp[M_TOT * D_MODEL];
__device__ float g_kp[M_TOT * D_MODEL];
__device__ float g_vp[M_TOT * D_MODEL];
__device__ int   g_mask_nz;        // monotone OR-flag; replay-idempotent (inputs fixed)

// ---------------------------------------------------------------------------
__device__ __forceinline__ unsigned f2tf(float x) {
    unsigned r;
    asm("cvt.rna.tf32.f32 %0, %1;" : "=r"(r) : "f"(x));
    return r;
}
__device__ __forceinline__ unsigned u2tf(unsigned raw) {   // raw fp32 bits -> tf32 bits
    return f2tf(__uint_as_float(raw));
}

__device__ __forceinline__ void mma8(float* d, const unsigned* a, const unsigned* b) {
    asm volatile(
        "mma.sync.aligned.m16n8k8.row.col.f32.tf32.tf32.f32 "
        "{%0,%1,%2,%3}, {%4,%5,%6,%7}, {%8,%9}, {%0,%1,%2,%3};\n"
        : "+f"(d[0]), "+f"(d[1]), "+f"(d[2]), "+f"(d[3])
        : "r"(a[0]), "r"(a[1]), "r"(a[2]), "r"(a[3]), "r"(b[0]), "r"(b[1]));
}

__device__ __forceinline__ void cp16(unsigned* smem_dst, const void* gsrc) {
    unsigned d = (unsigned)__cvta_generic_to_shared(smem_dst);
    asm volatile("cp.async.cg.shared.global [%0], [%1], 16;\n" :: "r"(d), "l"(gsrc));
}
#define CP_COMMIT asm volatile("cp.async.commit_group;\n" ::: "memory")
#define CP_WAIT0  asm volatile("cp.async.wait_group 0;\n" ::: "memory")

// 2^x, FMA/ALU only (x <= 0, clamped at -115). Degree-4 poly.
__device__ __forceinline__ float fast_exp2(float x) {
    x = fmaxf(x, -115.0f);
    float fy = x + 12582912.0f;
    int   k  = __float_as_int(fy);
    float f  = x - (fy - 12582912.0f);
    float p  = 9.61812e-3f;
    p = fmaf(p, f, 5.55041e-2f);
    p = fmaf(p, f, 2.40226507e-1f);
    p = fmaf(p, f, 6.93147182e-1f);
    p = fmaf(p, f, 1.0f);
    return __int_as_float(__float_as_int(p) + (k << 23));
}

// ---------------------------------------------------------------------------
// Projection GEMM on RAW fp32 inputs (tf32 cvt after LDS). R13-proven config.
// blockIdx.z==3 slice performs the mask-nonzero scan (folds check_mask launch).
// ---------------------------------------------------------------------------
__global__ __launch_bounds__(256, 2) void proj_tc6(
    const float* __restrict__ x0, const float* __restrict__ x1, const float* __restrict__ x2,
    const float* __restrict__ w0, const float* __restrict__ w1, const float* __restrict__ w2,
    const float* __restrict__ bq, const float* __restrict__ bk, const float* __restrict__ bv,
    float* __restrict__ y0, float* __restrict__ y1, float* __restrict__ y2,
    const int4* __restrict__ maskv)
{
    const int tid = threadIdx.x;
    if (blockIdx.z == 3) {
        // ---- mask scan slice: 256 CTAs x 256 threads, 16 int4 each ----
        const int gid = (blockIdx.y * 8 + blockIdx.x) * 256 + tid;
        int acc = 0;
#pragma unroll
        for (int j = 0; j < 16; j++) {
            int4 v = maskv[(size_t)j * 65536 + gid];
            acc |= v.x | v.y | v.z | v.w;
        }
        acc |= __shfl_xor_sync(0xffffffffu, acc, 16);
        acc |= __shfl_xor_sync(0xffffffffu, acc, 8);
        acc |= __shfl_xor_sync(0xffffffffu, acc, 4);
        acc |= __shfl_xor_sync(0xffffffffu, acc, 2);
        acc |= __shfl_xor_sync(0xffffffffu, acc, 1);
        __shared__ int wsh[8];
        if ((tid & 31) == 0) wsh[tid >> 5] = acc;
        __syncthreads();
        if (tid == 0) {
            int r = 0;
#pragma unroll
            for (int j = 0; j < 8; j++) r |= wsh[j];
            if (r) atomicOr(&g_mask_nz, 1);
        }
        return;
    }

    const int z = blockIdx.z;
    const float* X    = (z == 0) ? x0 : (z == 1) ? x1 : x2;
    const float* W    = (z == 0) ? w0 : (z == 1) ? w1 : w2;
    const float* bias = (z == 0) ? bq : (z == 1) ? bk : bv;
    float*       Y    = (z == 0) ? y0 : (z == 1) ? y1 : y2;
    const float oscale = (z == 0) ? 0.125f * LOG2E : 1.0f;

    extern __shared__ unsigned psm[];
    unsigned* As = psm;             // [2][128*36] raw fp32 bits
    unsigned* Bs = psm + 2 * 4608;

    const int lane = tid & 31, wid = tid >> 5;
    const int wm = wid >> 2, wn = wid & 3;
    const int g = lane >> 2, t = lane & 3;
    const int bm = blockIdx.y * 128, bn = blockIdx.x * 128;

    const int frow = tid >> 3;        // 0..31, +p*32
    const int fc4  = (tid & 7) * 4;   // 0..28

    float acc[4][4][4];
#pragma unroll
    for (int mi = 0; mi < 4; mi++)
#pragma unroll
        for (int nj = 0; nj < 4; nj++)
#pragma unroll
            for (int r = 0; r < 4; r++) acc[mi][nj][r] = 0.0f;

    {
        const float* Xs = X + (size_t)bm * D_MODEL + fc4;
        const float* Ws = W + (size_t)bn * D_MODEL + fc4;
#pragma unroll
        for (int p = 0; p < 4; p++) {
            int row = frow + p * 32;
            cp16(As + row * 36 + fc4, Xs + (size_t)row * D_MODEL);
            cp16(Bs + row * 36 + fc4, Ws + (size_t)row * D_MODEL);
        }
        CP_COMMIT;
    }

    for (int it = 0; it < 32; it++) {
        CP_WAIT0;
        __syncthreads();
        if (it < 31) {
            int buf = (it + 1) & 1;
            int k0 = (it + 1) * 32;
            const float* Xs = X + (size_t)bm * D_MODEL + k0 + fc4;
            const float* Ws = W + (size_t)bn * D_MODEL + k0 + fc4;
            unsigned* Ab = As + buf * 4608;
            unsigned* Bb = Bs + buf * 4608;
#pragma unroll
            for (int p = 0; p < 4; p++) {
                int row = frow + p * 32;
                cp16(Ab + row * 36 + fc4, Xs + (size_t)row * D_MODEL);
                cp16(Bb + row * 36 + fc4, Ws + (size_t)row * D_MODEL);
            }
            CP_COMMIT;
        }
        const unsigned* Ab = As + (it & 1) * 4608;
        const unsigned* Bb = Bs + (it & 1) * 4608;
#pragma unroll
        for (int kk = 0; kk < 4; kk++) {
            unsigned af[4][4], bf[4][2];
#pragma unroll
            for (int mi = 0; mi < 4; mi++) {
                int ba = (wm * 64 + mi * 16 + g) * 36 + kk * 8 + t;
                af[mi][0] = u2tf(Ab[ba]);     af[mi][1] = u2tf(Ab[ba + 8 * 36]);
                af[mi][2] = u2tf(Ab[ba + 4]); af[mi][3] = u2tf(Ab[ba + 8 * 36 + 4]);
            }
#pragma unroll
            for (int nj = 0; nj < 4; nj++) {
                int bb = (wn * 32 + nj * 8 + g) * 36 + kk * 8 + t;
                bf[nj][0] = u2tf(Bb[bb]); bf[nj][1] = u2tf(Bb[bb + 4]);
            }
#pragma unroll
            for (int mi = 0; mi < 4; mi++)
#pragma unroll
                for (int nj = 0; nj < 4; nj++)
                    mma8(acc[mi][nj], af[mi], bf[nj]);
        }
        __syncthreads();
    }

#pragma unroll
    for (int mi = 0; mi < 4; mi++) {
        int r0 = bm + wm * 64 + mi * 16 + g;
#pragma unroll
        for (int nj = 0; nj < 4; nj++) {
            int c = bn + wn * 32 + nj * 8 + 2 * t;
            float bb0 = bias[c], bb1 = bias[c + 1];
            float v0 = (acc[mi][nj][0] + bb0) * oscale;
            float v1 = (acc[mi][nj][1] + bb1) * oscale;
            float v2 = (acc[mi][nj][2] + bb0) * oscale;
            float v3 = (acc[mi][nj][3] + bb1) * oscale;
            *(float2*)(Y + (size_t)r0 * D_MODEL + c) =
                make_float2(__uint_as_float(f2tf(v0)), __uint_as_float(f2tf(v1)));
            *(float2*)(Y + (size_t)(r0 + 8) * D_MODEL + c) =
                make_float2(__uint_as_float(f2tf(v2)), __uint_as_float(f2tf(v3)));
        }
    }
}

// ---------------------------------------------------------------------------
// Flash attention (byte-identical to R10/R13 = proven champion config).
// exp2-domain online softmax, deferred l-reduction, maskless mask-add skip.
// 256 thr / 8 warps, q-tile 128 (16 rows/warp), key tiles of 64,
// double-buffered cp.async. Strides: Q/K 68, V 72 -> conflict-free.
// ---------------------------------------------------------------------------
__device__ __forceinline__ void p_relayout(const float* s, unsigned* a, int lane, int t) {
    const int srcA = (lane & 28) | (t >> 1);
    const int srcB = srcA + 2;
    float u0 = __shfl_sync(0xffffffffu, s[0], srcA);
    float u1 = __shfl_sync(0xffffffffu, s[1], srcA);
    float v0 = __shfl_sync(0xffffffffu, s[2], srcA);
    float v1 = __shfl_sync(0xffffffffu, s[3], srcA);
    float w0 = __shfl_sync(0xffffffffu, s[0], srcB);
    float w1 = __shfl_sync(0xffffffffu, s[1], srcB);
    float x0 = __shfl_sync(0xffffffffu, s[2], srcB);
    float x1 = __shfl_sync(0xffffffffu, s[3], srcB);
    bool odd = (t & 1);
    a[0] = f2tf(odd ? u1 : u0);
    a[1] = f2tf(odd ? v1 : v0);
    a[2] = f2tf(odd ? w1 : w0);
    a[3] = f2tf(odd ? x1 : x0);
}

__global__ __launch_bounds__(256, 2) void attn_tc4(
    const float* __restrict__ QP, const float* __restrict__ KP,
    const float* __restrict__ VP, const float* __restrict__ mask,
    float* __restrict__ out)
{
    extern __shared__ unsigned smbuf[];
    unsigned* Qs = smbuf;             // 128*68 = 8704 words
    unsigned* Ks = smbuf + 8704;      // 2 x 64*68 (4352 each)
    unsigned* Vs = smbuf + 17408;     // 2 x 64*72 (4608 each)

    const int tid = threadIdx.x, lane = tid & 31, wid = tid >> 5;
    const int g = lane >> 2, t = lane & 3;
    const int rw = wid * 16;
    const int q0 = blockIdx.x * 128;
    const int h = blockIdx.y, b = blockIdx.z;
    const size_t base = (size_t)b * SEQ * D_MODEL + (size_t)h * HEAD;
    const int has_mask = g_mask_nz;

    const int frow = tid >> 4;        // 0..15
    const int fc4  = (tid & 15) * 4;  // 0..60

    {
        const float* Qsrc = QP + base + (size_t)q0 * D_MODEL + fc4;
#pragma unroll
        for (int p = 0; p < 8; p++) {
            int row = frow + p * 16;
            cp16(Qs + row * 68 + fc4, Qsrc + (size_t)row * D_MODEL);
        }
        const float* Ksrc = KP + base + fc4;
        const float* Vsrc = VP + base + fc4;
#pragma unroll
        for (int p = 0; p < 4; p++) {
            int row = frow + p * 16;
            cp16(Ks + row * 68 + fc4, Ksrc + (size_t)row * D_MODEL);
            cp16(Vs + row * 72 + fc4, Vsrc + (size_t)row * D_MODEL);
        }
        CP_COMMIT;
    }

    float o[8][4];
#pragma unroll
    for (int nj = 0; nj < 8; nj++)
#pragma unroll
        for (int r = 0; r < 4; r++) o[nj][r] = 0.0f;
    float m0 = -1e30f, m1 = -1e30f;
    float l0 = 0.0f, l1 = 0.0f;   // lane-partial (reduced across t-lanes at end)

    const float* mp0 = mask + (size_t)(q0 + rw + g) * SEQ;
    const float* mp1 = mp0 + (size_t)8 * SEQ;

    for (int it = 0; it < SEQ / 64; it++) {
        CP_WAIT0;
        __syncthreads();
        if (it + 1 < SEQ / 64) {
            int buf = (it + 1) & 1;
            const float* Ksrc = KP + base + (size_t)(it + 1) * 64 * D_MODEL + fc4;
            const float* Vsrc = VP + base + (size_t)(it + 1) * 64 * D_MODEL + fc4;
            unsigned* Kb = Ks + buf * 4352;
            unsigned* Vb = Vs + buf * 4608;
#pragma unroll
            for (int p = 0; p < 4; p++) {
                int row = frow + p * 16;
                cp16(Kb + row * 68 + fc4, Ksrc + (size_t)row * D_MODEL);
                cp16(Vb + row * 72 + fc4, Vsrc + (size_t)row * D_MODEL);
            }
            CP_COMMIT;
        }
        const unsigned* Kc = Ks + (it & 1) * 4352;
        const unsigned* Vc = Vs + (it & 1) * 4608;
        const int k0 = it * 64;

        // ---- S = Q @ K^T (scores in exp2 domain; Q prescaled) ----
        float s[8][4];
#pragma unroll
        for (int nj = 0; nj < 8; nj++)
#pragma unroll
            for (int r = 0; r < 4; r++) s[nj][r] = 0.0f;

#pragma unroll
        for (int kc = 0; kc < 8; kc++) {
            unsigned a[4];
            int qb = (rw + g) * 68 + kc * 8 + t;
            a[0] = Qs[qb];     a[1] = Qs[qb + 8 * 68];
            a[2] = Qs[qb + 4]; a[3] = Qs[qb + 8 * 68 + 4];
#pragma unroll
            for (int nj = 0; nj < 8; nj++) {
                unsigned bf[2];
                int kb = (nj * 8 + g) * 68 + kc * 8 + t;
                bf[0] = Kc[kb]; bf[1] = Kc[kb + 4];
                mma8(s[nj], a, bf);
            }
        }

        // ---- mask (only if nonzero) + row max ----
        float mx0 = -1e30f, mx1 = -1e30f;
        if (has_mask) {
#pragma unroll
            for (int nj = 0; nj < 8; nj++) {
                float2 mk0 = *(const float2*)(mp0 + k0 + nj * 8 + 2 * t);
                float2 mk1 = *(const float2*)(mp1 + k0 + nj * 8 + 2 * t);
                s[nj][0] = fmaf(mk0.x, LOG2E, s[nj][0]);
                s[nj][1] = fmaf(mk0.y, LOG2E, s[nj][1]);
                s[nj][2] = fmaf(mk1.x, LOG2E, s[nj][2]);
                s[nj][3] = fmaf(mk1.y, LOG2E, s[nj][3]);
                mx0 = fmaxf(mx0, fmaxf(s[nj][0], s[nj][1]));
                mx1 = fmaxf(mx1, fmaxf(s[nj][2], s[nj][3]));
            }
        } else {
#pragma unroll
            for (int nj = 0; nj < 8; nj++) {
                mx0 = fmaxf(mx0, fmaxf(s[nj][0], s[nj][1]));
                mx1 = fmaxf(mx1, fmaxf(s[nj][2], s[nj][3]));
            }
        }
        mx0 = fmaxf(mx0, __shfl_xor_sync(0xffffffffu, mx0, 1));
        mx0 = fmaxf(mx0, __shfl_xor_sync(0xffffffffu, mx0, 2));
        mx1 = fmaxf(mx1, __shfl_xor_sync(0xffffffffu, mx1, 1));
        mx1 = fmaxf(mx1, __shfl_xor_sync(0xffffffffu, mx1, 2));

        float mn0 = fmaxf(m0, mx0), mn1 = fmaxf(m1, mx1);
        float c0 = fast_exp2(m0 - mn0), c1 = fast_exp2(m1 - mn1);
        float sum0 = 0.0f, sum1 = 0.0f;
#pragma unroll
        for (int nj = 0; nj < 8; nj++) {
            s[nj][0] = fast_exp2(s[nj][0] - mn0);
            s[nj][1] = fast_exp2(s[nj][1] - mn0);
            s[nj][2] = fast_exp2(s[nj][2] - mn1);
            s[nj][3] = fast_exp2(s[nj][3] - mn1);
            sum0 += s[nj][0] + s[nj][1];
            sum1 += s[nj][2] + s[nj][3];
        }
        l0 = l0 * c0 + sum0;  l1 = l1 * c1 + sum1;
        m0 = mn0;             m1 = mn1;
#pragma unroll
        for (int nj = 0; nj < 8; nj++) {
            o[nj][0] *= c0; o[nj][1] *= c0;
            o[nj][2] *= c1; o[nj][3] *= c1;
        }

        // ---- O += P @ V (P via shfl relayout) ----
#pragma unroll
        for (int kp = 0; kp < 4; kp++) {
            unsigned pe[4], po[4];
            p_relayout(s[2 * kp],     pe, lane, t);
            p_relayout(s[2 * kp + 1], po, lane, t);
#pragma unroll
            for (int oj = 0; oj < 8; oj++) {
                unsigned bA[2], bB[2];
                int vb = (kp * 16 + t) * 72 + oj * 8 + g;
                bA[0] = Vc[vb];           bA[1] = Vc[vb + 4 * 72];
                bB[0] = Vc[vb + 8 * 72];  bB[1] = Vc[vb + 12 * 72];
                mma8(o[oj], pe, bA);
                mma8(o[oj], po, bB);
            }
        }
    }

    // final cross-lane reduction of deferred l
    l0 += __shfl_xor_sync(0xffffffffu, l0, 1);
    l0 += __shfl_xor_sync(0xffffffffu, l0, 2);
    l1 += __shfl_xor_sync(0xffffffffu, l1, 1);
    l1 += __shfl_xor_sync(0xffffffffu, l1, 2);

    float inv0 = 1.0f / l0, inv1 = 1.0f / l1;
    const int r0g = q0 + rw + g;
    float* o0 = out + base + (size_t)r0g * D_MODEL;
    float* o1 = o0 + (size_t)8 * D_MODEL;
#pragma unroll
    for (int nj = 0; nj < 8; nj++) {
        *(float2*)(o0 + nj * 8 + 2 * t) = make_float2(o[nj][0] * inv0, o[nj][1] * inv0);
        *(float2*)(o1 + nj * 8 + 2 * t) = make_float2(o[nj][2] * inv1, o[nj][3] * inv1);
    }
}

// ---------------------------------------------------------------------------

extern "C" void kernel_launch(void* const* d_in, const int* in_sizes, int n_in,
                              void* d_out, int out_size)
{
    const float* q    = (const float*)d_in[0];
    const float* k    = (const float*)d_in[1];
    const float* v    = (const float*)d_in[2];
    const float* mask = (const float*)d_in[3];
    const float* Wq   = (const float*)d_in[4];
    const float* bq   = (const float*)d_in[5];
    const float* Wk   = (const float*)d_in[6];
    const float* bk   = (const float*)d_in[7];
    const float* Wv   = (const float*)d_in[8];
    const float* bv   = (const float*)d_in[9];
    float* out = (float*)d_out;

    float *qp, *kp, *vp;
    cudaGetSymbolAddress((void**)&qp, g_qp);
    cudaGetSymbolAddress((void**)&kp, g_kp);
    cudaGetSymbolAddress((void**)&vp, g_vp);

    const int psmem = 4 * 4608 * (int)sizeof(unsigned);   // 73728 B
    cudaFuncSetAttribute(proj_tc6, cudaFuncAttributeMaxDynamicSharedMemorySize, psmem);
    proj_tc6<<<dim3(D_MODEL / 128, M_TOT / 128, 4), 256, psmem>>>(
        q, k, v, Wq, Wk, Wv, bq, bk, bv, qp, kp, vp, (const int4*)mask);

    const int asmem = (8704 + 2 * 4352 + 2 * 4608) * (int)sizeof(unsigned);  // 106496 B
    cudaFuncSetAttribute(attn_tc4, cudaFuncAttributeMaxDynamicSharedMemorySize, asmem);
    attn_tc4<<<dim3(SEQ / 128, N_HEADS, BATCH), 256, asmem>>>(qp, kp, vp, mask, out);
}